// round 1
// baseline (speedup 1.0000x reference)
#include <cuda_runtime.h>
#include <cstdint>
#include <math_constants.h>

// Problem constants (fixed shapes for this problem)
#define DIM      256
#define NPIX     65536      // DIM*DIM
#define HO       128
#define NOUT     16384      // HO*HO
#define HALF     32768      // NPIX/2
#define NTHREADS 1024
#define OUT_PER_THREAD 16   // NOUT / NTHREADS

// L2-resident compressed index table (4 uint16 per output pixel = 128 KB)
__device__ uint16_t g_idx16[NOUT * 4];

// ---------------------------------------------------------------------------
// Pass 0: compress gather_idx (int64 OR int32, autodetected) -> uint16.
// gather_idx is a permutation of [0,65536): among any 8 sampled entries at
// most one can be zero, so "first 8 odd u32 words all zero" <=> int64 layout.
// ---------------------------------------------------------------------------
__global__ void cvt_idx_kernel(const uint32_t* __restrict__ src) {
    bool is64 = true;
#pragma unroll
    for (int i = 0; i < 8; i++) is64 &= (src[2 * i + 1] == 0u);
    int t = blockIdx.x * blockDim.x + threadIdx.x;  // 0 .. 65535
    uint32_t v = is64 ? src[2 * t] : src[t];
    g_idx16[t] = (uint16_t)v;
}

// ---------------------------------------------------------------------------
// Main kernel: one CTA per (b,c) plane. Stage each half-plane (128 KB) in
// dynamic smem via coalesced float4 loads, gather with LDS (random smem is
// ~3 cyc/warp vs 32 L1tex wavefronts for divergent LDG), accumulate maxes
// in registers, write coalesced.
// ---------------------------------------------------------------------------
extern __shared__ float sdata[];  // HALF floats = 128 KB dynamic

__global__ void __launch_bounds__(NTHREADS, 1)
pool_kernel(const float* __restrict__ x, float* __restrict__ out) {
    const int plane = blockIdx.x;
    const float* __restrict__ xp = x + (size_t)plane * NPIX;
    const int t = threadIdx.x;

    float m[OUT_PER_THREAD];
#pragma unroll
    for (int k = 0; k < OUT_PER_THREAD; k++) m[k] = -CUDART_INF_F;

    const uint2* __restrict__ idxv = reinterpret_cast<const uint2*>(g_idx16);

#pragma unroll
    for (int h = 0; h < 2; h++) {
        const unsigned base = h * HALF;

        // Stage half-plane into smem: 8192 float4, 8 per thread, coalesced.
        const float4* __restrict__ src = reinterpret_cast<const float4*>(xp + base);
        float4* dst = reinterpret_cast<float4*>(sdata);
#pragma unroll
        for (int w = 0; w < 8; w++) dst[t + w * NTHREADS] = src[t + w * NTHREADS];
        __syncthreads();

        // Gather: each thread owns outputs o = t + k*1024 (coalesced idx/out).
#pragma unroll
        for (int k = 0; k < OUT_PER_THREAD; k++) {
            const int o = t + k * NTHREADS;
            const uint2 p = __ldg(&idxv[o]);  // 4 x uint16 packed
            const unsigned i0 = p.x & 0xFFFFu;
            const unsigned i1 = p.x >> 16;
            const unsigned i2 = p.y & 0xFFFFu;
            const unsigned i3 = p.y >> 16;
            unsigned r;
            r = i0 - base; if (r < HALF) m[k] = fmaxf(m[k], sdata[r]);
            r = i1 - base; if (r < HALF) m[k] = fmaxf(m[k], sdata[r]);
            r = i2 - base; if (r < HALF) m[k] = fmaxf(m[k], sdata[r]);
            r = i3 - base; if (r < HALF) m[k] = fmaxf(m[k], sdata[r]);
        }
        __syncthreads();  // protect smem before next half overwrites it
    }

    float* __restrict__ op = out + (size_t)plane * NOUT;
#pragma unroll
    for (int k = 0; k < OUT_PER_THREAD; k++) op[t + k * NTHREADS] = m[k];
}

// ---------------------------------------------------------------------------
// Launch
// ---------------------------------------------------------------------------
extern "C" void kernel_launch(void* const* d_in, const int* in_sizes, int n_in,
                              void* d_out, int out_size) {
    const float*    x    = (const float*)d_in[0];
    const uint32_t* gidx = (const uint32_t*)d_in[1];
    float*          out  = (float*)d_out;

    const int planes = in_sizes[0] / NPIX;  // 16*64 = 1024

    static bool attr_set = false;
    // cudaFuncSetAttribute is immediate (not a stream op) -> capture-safe,
    // and idempotent; call unconditionally to keep kernel_launch stateless.
    cudaFuncSetAttribute(pool_kernel,
                         cudaFuncAttributeMaxDynamicSharedMemorySize,
                         HALF * (int)sizeof(float));
    (void)attr_set;

    cvt_idx_kernel<<<NOUT * 4 / 256, 256>>>(gidx);
    pool_kernel<<<planes, NTHREADS, HALF * sizeof(float)>>>(x, out);
}